// round 10
// baseline (speedup 1.0000x reference)
#include <cuda_runtime.h>
#include <math.h>

#define NCB   10
#define KCB   2048
#define DD    256
#define SEMD  256
#define W2VD  1024
#define BT    16384              // B*T tokens
#define ZQ_ELEMS (BT*DD)         // 4194304
#define CODES_OFF ZQ_ELEMS
#define VQ_OFF   (CODES_OFF + BT*NCB)
#define SEM_OFF  (VQ_OFF + 1)
#define ASTR  68                 // A smem row stride (64 slots + pad)
#define APAD  68                 // gemm kernels' A stride

// -------- device scratch (no runtime allocation allowed) --------
__device__ float g_zq1[ZQ_ELEMS];        // z_q of codebook 0 (semantic head input)
__device__ float g_H[BT*SEMD];           // semantic hidden
__device__ float g_Et[NCB*DD*KCB + 2*KCB]; // E transposed [cb][d][k] + prefetch pad
__device__ float g_en[NCB*KCB];          // ||e_k||^2 per codebook
__device__ float g_vqp[NCB];             // per-codebook sum of (q-r)^2
__device__ float g_semsum;               // sum of (pred-target)^2

// packed fp32x2 FMA (sm_103a): two bitwise-exact IEEE fp32 FMAs per issue slot
__device__ __forceinline__ void fma2(unsigned long long& d,
                                     unsigned long long a, unsigned long long b) {
    asm("fma.rn.f32x2 %0, %1, %2, %0;" : "+l"(d) : "l"(a), "l"(b));
}
__device__ __forceinline__ unsigned long long dup2(float a) {
    unsigned long long r;
    asm("mov.b64 %0, {%1, %1};" : "=l"(r) : "f"(a));
    return r;
}
__device__ __forceinline__ void unpk(float& lo, float& hi, unsigned long long v) {
    asm("mov.b64 {%0, %1}, %2;" : "=f"(lo), "=f"(hi) : "l"(v));
}

// ---------------- E transpose: g_Et[cb][d][k] = E[cb][k][d] ----------------
__global__ void k_trans(const float* __restrict__ E) {
    __shared__ float tile[64][65];
    int kt = blockIdx.x, dt = blockIdx.y, cb = blockIdx.z;
    int tid = threadIdx.x;
    const float* Ein = E + (size_t)cb * KCB * DD;
    float* Eout = g_Et + (size_t)cb * DD * KCB;
    #pragma unroll
    for (int i = 0; i < 16; i++) {
        int idx = i * 256 + tid;
        int r = idx >> 6, c = idx & 63;
        tile[r][c] = Ein[(size_t)(kt * 64 + r) * DD + dt * 64 + c];
    }
    __syncthreads();
    #pragma unroll
    for (int i = 0; i < 16; i++) {
        int idx = i * 256 + tid;
        int r = idx >> 6, c = idx & 63;
        Eout[(size_t)(dt * 64 + r) * KCB + kt * 64 + c] = tile[c][r];
    }
}

// ---------------- codeword norms (summation order preserved) ----------------
__global__ void k_enorm(const float* __restrict__ E) {
    int w = (blockIdx.x * blockDim.x + threadIdx.x) >> 5;
    int lane = threadIdx.x & 31;
    if (w >= NCB * KCB) return;
    const float* e = E + (size_t)w * DD;
    float s = 0.f;
    #pragma unroll
    for (int k = 0; k < 8; k++) { float v = e[lane + 32 * k]; s += v * v; }
    #pragma unroll
    for (int off = 16; off; off >>= 1) s += __shfl_down_sync(0xffffffffu, s, off);
    if (!lane) g_en[w] = s;
}

// ---------------- init: zero loss accumulators only ----------------
__global__ void k_init() {
    int i = threadIdx.x;
    if (i < NCB) g_vqp[i] = 0.f;
    if (i == NCB) g_semsum = 0.f;
}

// ---------------- fully fused RVQ: barrier-free mainloop ----------------
// 256 threads = 8 warps, 64 tokens per CTA (grid 256 -> zero padding work).
// Warp wy owns CODEWORD slice [nt*256+wy*32, +32); lanes: tg=lane>>2 token
// group, cg=lane&3 cw sub-slice. B comes straight from L2 via per-thread
// __ldg (no smem staging, no cp.async, NO per-chunk __syncthreads -- warps
// free-run through each codebook; only 2 barriers per cb for merge/update).
__global__ void __launch_bounds__(256, 2)
k_rvq(const float* __restrict__ z, const float* __restrict__ E, float* __restrict__ out) {
    extern __shared__ float sm[];
    float* Asm  = sm;                       // [257][ASTR] residual (token minor)
    float* xxs  = sm + 257 * ASTR;          // [64]
    float* redv = xxs + 64;                 // [8 warps][64 tokens]
    int*   redi = (int*)(redv + 512);       // [8 warps][64 tokens]

    int tid = threadIdx.x;
    int lane = tid & 31, wy = tid >> 5;
    int tg = lane >> 2, cg = lane & 3;
    int m0 = blockIdx.x * 64;

    // load A tile (64 tokens x 256 d) from z, transposed into Asm[d][slot]
    const float4* Ag = reinterpret_cast<const float4*>(z + (size_t)m0 * DD);
    #pragma unroll
    for (int i = 0; i < 16; i++) {
        int f = tid + 256 * i;
        int tok = f >> 6, seg = f & 63;
        float4 v = Ag[f];
        int db = seg * 4;
        Asm[(db + 0) * ASTR + tok] = v.x;
        Asm[(db + 1) * ASTR + tok] = v.y;
        Asm[(db + 2) * ASTR + tok] = v.z;
        Asm[(db + 3) * ASTR + tok] = v.w;
    }

    // initial ||x||^2 per token (ascending j, shfl_down tree)
    #pragma unroll
    for (int r = 0; r < 8; r++) {
        int tok = m0 + wy * 8 + r;
        const float* row = z + (size_t)tok * DD;
        float s = 0.f;
        #pragma unroll
        for (int k = 0; k < 8; k++) { float v = row[lane + 32 * k]; s += v * v; }
        #pragma unroll
        for (int off = 16; off; off >>= 1) s += __shfl_down_sync(0xffffffffu, s, off);
        if (!lane) xxs[wy * 8 + r] = s;
    }
    __syncthreads();

    const int boff = wy * 32 + cg * 8;      // thread's cw offset inside a 256-cw tile

    for (int cb = 0; cb < NCB; cb++) {
        const float* Et  = g_Et + (size_t)cb * DD * KCB;
        const float* Ecb = E + (size_t)cb * KCB * DD;
        const float* enb = g_en + cb * KCB;

        float mv[8]; int mi[8];
        #pragma unroll
        for (int r = 0; r < 8; r++) { mv[r] = INFINITY; mi[r] = 0; }
        unsigned long long acc[8][4];
        #pragma unroll
        for (int r = 0; r < 8; r++)
            #pragma unroll
            for (int q = 0; q < 4; q++) acc[r][q] = 0ull;

        for (int nt = 0; nt < 8; nt++) {               // 8 n-tiles of 256 cw
            const float* bcol = Et + nt * 256 + boff;  // thread's cw slice

            // preload d=0 operands
            float4 b0 = __ldg(reinterpret_cast<const float4*>(bcol));
            float4 b1 = __ldg(reinterpret_cast<const float4*>(bcol + 4));
            float4 a0 = *reinterpret_cast<const float4*>(&Asm[tg * 8]);
            float4 a1 = *reinterpret_cast<const float4*>(&Asm[tg * 8 + 4]);

            #pragma unroll 16
            for (int d = 0; d < 256; d++) {            // full D sweep, no syncs
                // prefetch d+1 (pads make the final read safe)
                float4 nb0 = __ldg(reinterpret_cast<const float4*>(bcol + (size_t)(d + 1) * KCB));
                float4 nb1 = __ldg(reinterpret_cast<const float4*>(bcol + (size_t)(d + 1) * KCB + 4));
                float4 na0 = *reinterpret_cast<const float4*>(&Asm[(d + 1) * ASTR + tg * 8]);
                float4 na1 = *reinterpret_cast<const float4*>(&Asm[(d + 1) * ASTR + tg * 8 + 4]);

                ulonglong2 bb0 = *reinterpret_cast<ulonglong2*>(&b0);
                ulonglong2 bb1 = *reinterpret_cast<ulonglong2*>(&b1);
                float a[8] = {a0.x, a0.y, a0.z, a0.w, a1.x, a1.y, a1.z, a1.w};
                #pragma unroll
                for (int r = 0; r < 8; r++) {
                    unsigned long long a2 = dup2(a[r]);
                    fma2(acc[r][0], a2, bb0.x);
                    fma2(acc[r][1], a2, bb0.y);
                    fma2(acc[r][2], a2, bb1.x);
                    fma2(acc[r][3], a2, bb1.y);
                }
                b0 = nb0; b1 = nb1; a0 = na0; a1 = na1;
            }

            // n-tile argmin epilogue
            int n0 = nt * 256;
            float2 e01[4];
            #pragma unroll
            for (int q = 0; q < 4; q++)
                e01[q] = __ldg(reinterpret_cast<const float2*>(&enb[n0 + boff + q * 2]));
            #pragma unroll
            for (int r = 0; r < 8; r++) {
                float xr = xxs[tg * 8 + r];
                #pragma unroll
                for (int q = 0; q < 4; q++) {
                    int kb = n0 + boff + q * 2;
                    float lo, hi;
                    unpk(lo, hi, acc[r][q]);
                    float s0 = (xr - 2.0f * lo) + e01[q].x;
                    float s1 = (xr - 2.0f * hi) + e01[q].y;
                    if (s0 < mv[r]) { mv[r] = s0; mi[r] = kb; }
                    if (s1 < mv[r]) { mv[r] = s1; mi[r] = kb + 1; }
                    acc[r][q] = 0ull;
                }
            }
        }

        // reduce across the 4 cg lanes sharing a token group (tie: smaller index)
        #pragma unroll
        for (int off = 1; off < 4; off <<= 1) {
            #pragma unroll
            for (int r = 0; r < 8; r++) {
                float ov = __shfl_xor_sync(0xffffffffu, mv[r], off);
                int   oi = __shfl_xor_sync(0xffffffffu, mi[r], off);
                if (ov < mv[r] || (ov == mv[r] && oi < mi[r])) { mv[r] = ov; mi[r] = oi; }
            }
        }
        // publish per-warp candidates (warp cw sets are disjoint)
        if (cg == 0) {
            #pragma unroll
            for (int r = 0; r < 8; r++) {
                redv[wy * 64 + tg * 8 + r] = mv[r];
                redi[wy * 64 + tg * 8 + r] = mi[r];
            }
        }
        __syncthreads();

        // final merge + straight-through update: warp wy owns tokens wy*8..+8
        {
            int fidx[8];
            #pragma unroll
            for (int r = 0; r < 8; r++) {
                int slot = wy * 8 + r;
                float bv = redv[slot]; int bi = redi[slot];
                #pragma unroll
                for (int w = 1; w < 8; w++) {
                    float v = redv[w * 64 + slot]; int i = redi[w * 64 + slot];
                    if (v < bv || (v == bv && i < bi)) { bv = v; bi = i; }
                }
                fidx[r] = bi;
            }
            float sl = 0.f;
            #pragma unroll
            for (int r = 0; r < 8; r++) {
                int slot = wy * 8 + r;
                int tok = m0 + slot;
                int idx = fidx[r];
                const float* qrow = Ecb + (size_t)idx * DD;
                float* orow = out + (size_t)tok * DD;
                float* zrow = g_zq1 + (size_t)tok * DD;
                float sx = 0.f;
                #pragma unroll
                for (int j = 0; j < 8; j++) {
                    int d = lane + 32 * j;
                    float rr = Asm[d * ASTR + slot];
                    float q  = __ldg(&qrow[d]);
                    float df = q - rr;                 // fl(q - r)
                    float zq = rr + df;                // straight-through, jax order
                    float nr = rr - zq;                // new residual
                    if (cb == 0) { orow[d] = zq; zrow[d] = zq; }  // fl(0+zq)==zq
                    else orow[d] += zq;                // z_q_total accumulation
                    Asm[d * ASTR + slot] = nr;
                    sl += df * df;
                    sx += nr * nr;
                }
                #pragma unroll
                for (int off = 16; off; off >>= 1) sx += __shfl_down_sync(0xffffffffu, sx, off);
                if (lane == 0) {
                    xxs[slot] = sx;
                    out[CODES_OFF + tok * NCB + cb] = (float)idx;
                }
            }
            #pragma unroll
            for (int off = 16; off; off >>= 1) sl += __shfl_xor_sync(0xffffffffu, sl, off);
            if (lane == 0) atomicAdd(&g_vqp[cb], sl);
        }

        __syncthreads();   // Asm/xxs/red visible block-wide before next codebook
    }
}

// ---------------- semantic head GEMM1: H = gelu(zq1 @ W1 + b1) ----------------
__global__ void __launch_bounds__(256, 2)
k_gemm1(const float* __restrict__ W1, const float* __restrict__ b1) {
    extern __shared__ float sm[];
    float* Asm = sm;                  // [256][APAD]
    float* Bs  = sm + 256 * APAD;     // [16][APAD]
    int tid = threadIdx.x, tx = tid & 15, ty = tid >> 4;
    int m0 = blockIdx.x * 64, n0 = blockIdx.y * 64;

    const float4* Ag = reinterpret_cast<const float4*>(g_zq1 + (size_t)m0 * DD);
    #pragma unroll
    for (int i = 0; i < 16; i++) {
        int f = tid + 256 * i;
        int tok = f >> 6, seg = f & 63;
        float4 v = Ag[tok * 64 + seg];
        int db = seg * 4;
        Asm[(db + 0) * APAD + tok] = v.x;
        Asm[(db + 1) * APAD + tok] = v.y;
        Asm[(db + 2) * APAD + tok] = v.z;
        Asm[(db + 3) * APAD + tok] = v.w;
    }
    __syncthreads();

    unsigned long long acc[4][2];
    #pragma unroll
    for (int r = 0; r < 4; r++) { acc[r][0] = 0ull; acc[r][1] = 0ull; }

    for (int dc = 0; dc < 16; dc++) {
        int dk = tid >> 4, nseg = tid & 15;
        float4 v = *reinterpret_cast<const float4*>(&W1[(size_t)(dc * 16 + dk) * SEMD + n0 + nseg * 4]);
        *reinterpret_cast<float4*>(&Bs[dk * APAD + nseg * 4]) = v;
        __syncthreads();
        #pragma unroll
        for (int kk = 0; kk < 16; kk++) {
            float4 av = *reinterpret_cast<const float4*>(&Asm[(dc * 16 + kk) * APAD + ty * 4]);
            ulonglong2 bb = *reinterpret_cast<const ulonglong2*>(&Bs[kk * APAD + tx * 4]);
            float a[4] = {av.x, av.y, av.z, av.w};
            #pragma unroll
            for (int r = 0; r < 4; r++) {
                unsigned long long a2 = dup2(a[r]);
                fma2(acc[r][0], a2, bb.x);
                fma2(acc[r][1], a2, bb.y);
            }
        }
        __syncthreads();
    }
    #pragma unroll
    for (int r = 0; r < 4; r++)
        #pragma unroll
        for (int q = 0; q < 2; q++) {
            int m = m0 + ty * 4 + r, n = n0 + tx * 4 + q * 2;
            float lo, hi;
            unpk(lo, hi, acc[r][q]);
            float x0 = lo + __ldg(&b1[n]);
            float x1 = hi + __ldg(&b1[n + 1]);
            g_H[(size_t)m * SEMD + n]     = 0.5f * x0 * (1.0f + erff(x0 * 0.70710678118654752f));
            g_H[(size_t)m * SEMD + n + 1] = 0.5f * x1 * (1.0f + erff(x1 * 0.70710678118654752f));
        }
}

// ---------------- semantic head GEMM2 + fused MSE reduction ----------------
__global__ void __launch_bounds__(256, 2)
k_gemm2(const float* __restrict__ W2, const float* __restrict__ b2, const float* __restrict__ tgt) {
    extern __shared__ float sm[];
    float* Asm = sm;
    float* Bs  = sm + 256 * APAD;
    int tid = threadIdx.x, tx = tid & 15, ty = tid >> 4;
    int m0 = blockIdx.x * 64, n0 = blockIdx.y * 64;

    const float4* Ag = reinterpret_cast<const float4*>(g_H + (size_t)m0 * SEMD);
    #pragma unroll
    for (int i = 0; i < 16; i++) {
        int f = tid + 256 * i;
        int tok = f >> 6, seg = f & 63;
        float4 v = Ag[tok * 64 + seg];
        int db = seg * 4;
        Asm[(db + 0) * APAD + tok] = v.x;
        Asm[(db + 1) * APAD + tok] = v.y;
        Asm[(db + 2) * APAD + tok] = v.z;
        Asm[(db + 3) * APAD + tok] = v.w;
    }
    __syncthreads();

    unsigned long long acc[4][2];
    #pragma unroll
    for (int r = 0; r < 4; r++) { acc[r][0] = 0ull; acc[r][1] = 0ull; }

    for (int dc = 0; dc < 16; dc++) {
        int dk = tid >> 4, nseg = tid & 15;
        float4 v = *reinterpret_cast<const float4*>(&W2[(size_t)(dc * 16 + dk) * W2VD + n0 + nseg * 4]);
        *reinterpret_cast<float4*>(&Bs[dk * APAD + nseg * 4]) = v;
        __syncthreads();
        #pragma unroll
        for (int kk = 0; kk < 16; kk++) {
            float4 av = *reinterpret_cast<const float4*>(&Asm[(dc * 16 + kk) * APAD + ty * 4]);
            ulonglong2 bb = *reinterpret_cast<const ulonglong2*>(&Bs[kk * APAD + tx * 4]);
            float a[4] = {av.x, av.y, av.z, av.w};
            #pragma unroll
            for (int r = 0; r < 4; r++) {
                unsigned long long a2 = dup2(a[r]);
                fma2(acc[r][0], a2, bb.x);
                fma2(acc[r][1], a2, bb.y);
            }
        }
        __syncthreads();
    }

    float ls = 0.f;
    #pragma unroll
    for (int r = 0; r < 4; r++)
        #pragma unroll
        for (int q = 0; q < 2; q++) {
            int m = m0 + ty * 4 + r, n = n0 + tx * 4 + q * 2;
            float lo, hi;
            unpk(lo, hi, acc[r][q]);
            float p0 = lo + __ldg(&b2[n]);
            float p1 = hi + __ldg(&b2[n + 1]);
            float d0 = p0 - __ldg(&tgt[(size_t)m * W2VD + n]);
            float d1 = p1 - __ldg(&tgt[(size_t)m * W2VD + n + 1]);
            ls += d0 * d0;
            ls += d1 * d1;
        }
    __shared__ float red[8];
    int lane = tid & 31, w = tid >> 5;
    #pragma unroll
    for (int off = 16; off; off >>= 1) ls += __shfl_xor_sync(0xffffffffu, ls, off);
    if (!lane) red[w] = ls;
    __syncthreads();
    if (tid < 8) {
        float t = red[tid];
        #pragma unroll
        for (int off = 4; off; off >>= 1) t += __shfl_xor_sync(0xffu, t, off);
        if (tid == 0) atomicAdd(&g_semsum, t);
    }
}

// ---------------- finalize scalars ----------------
__global__ void k_fin(float* __restrict__ out) {
    if (threadIdx.x == 0) {
        float vq = 0.f;
        #pragma unroll
        for (int i = 0; i < NCB; i++) {
            float m = g_vqp[i] * (1.0f / 4194304.0f);   // mean over B*T*D
            vq += m + 0.25f * m;                         // embedding + COMMIT*commitment
        }
        out[VQ_OFF] = vq;
        out[SEM_OFF] = g_semsum * (1.0f / 16777216.0f);  // mean over B*T*W2V
    }
}

// ---------------- launch ----------------
extern "C" void kernel_launch(void* const* d_in, const int* in_sizes, int n_in,
                              void* d_out, int out_size) {
    const float* z   = (const float*)d_in[0];
    const float* w2v = (const float*)d_in[1];
    const float* E   = (const float*)d_in[2];
    const float* W1  = (const float*)d_in[3];
    const float* b1  = (const float*)d_in[4];
    const float* W2  = (const float*)d_in[5];
    const float* b2  = (const float*)d_in[6];
    float* out = (float*)d_out;

    // Asm 257*68 + xxs 64 + redv 512 + redi 512 = 18564 floats = 74,256 B
    const int ARG_SMEM  = (257 * ASTR + 64 + 512 + 512) * 4;
    const int GEMM_SMEM = (256 * APAD + 16 * APAD) * 4;              // 73,984 B
    cudaFuncSetAttribute(k_rvq,   cudaFuncAttributeMaxDynamicSharedMemorySize, ARG_SMEM);
    cudaFuncSetAttribute(k_gemm1, cudaFuncAttributeMaxDynamicSharedMemorySize, GEMM_SMEM);
    cudaFuncSetAttribute(k_gemm2, cudaFuncAttributeMaxDynamicSharedMemorySize, GEMM_SMEM);

    k_trans<<<dim3(KCB / 64, DD / 64, NCB), 256>>>(E);
    k_enorm<<<(NCB * KCB * 32 + 255) / 256, 256>>>(E);
    k_init<<<1, 32>>>();

    k_rvq<<<BT / 64, 256, ARG_SMEM>>>(z, E, out);

    k_gemm1<<<dim3(BT / 64, SEMD / 64), 256, GEMM_SMEM>>>(W1, b1);
    k_gemm2<<<dim3(BT / 64, W2VD / 64), 256, GEMM_SMEM>>>(W2, b2, w2v);
    k_fin<<<1, 32>>>(out);
}

// round 11
// speedup vs baseline: 1.0421x; 1.0421x over previous
#include <cuda_runtime.h>
#include <math.h>

#define NCB   10
#define KCB   2048
#define DD    256
#define SEMD  256
#define W2VD  1024
#define BT    16384              // B*T tokens
#define ZQ_ELEMS (BT*DD)         // 4194304
#define CODES_OFF ZQ_ELEMS
#define VQ_OFF   (CODES_OFF + BT*NCB)
#define SEM_OFF  (VQ_OFF + 1)
#define ASTR  68                 // A smem row stride (64 slots + pad)
#define APAD  68                 // gemm kernels' A stride

// -------- device scratch (no runtime allocation allowed) --------
__device__ float g_zq1[ZQ_ELEMS];        // z_q of codebook 0 (semantic head input)
__device__ float g_H[BT*SEMD];           // semantic hidden
__device__ float g_Et[NCB*DD*KCB];       // E transposed [cb][d][k]
__device__ float g_en[NCB*KCB];          // ||e_k||^2 per codebook
__device__ float g_vqp[NCB];             // per-codebook sum of (q-r)^2
__device__ float g_semsum;               // sum of (pred-target)^2

// packed fp32x2 FMA (sm_103a): two bitwise-exact IEEE fp32 FMAs per issue slot
__device__ __forceinline__ void fma2(unsigned long long& d,
                                     unsigned long long a, unsigned long long b) {
    asm("fma.rn.f32x2 %0, %1, %2, %0;" : "+l"(d) : "l"(a), "l"(b));
}
__device__ __forceinline__ unsigned long long dup2(float a) {
    unsigned long long r;
    asm("mov.b64 %0, {%1, %1};" : "=l"(r) : "f"(a));
    return r;
}
__device__ __forceinline__ void unpk(float& lo, float& hi, unsigned long long v) {
    asm("mov.b64 {%0, %1}, %2;" : "=f"(lo), "=f"(hi) : "l"(v));
}
__device__ __forceinline__ void cp16(void* smem_dst, const void* gsrc) {
    unsigned s = (unsigned)__cvta_generic_to_shared(smem_dst);
    asm volatile("cp.async.cg.shared.global [%0], [%1], 16;" :: "r"(s), "l"(gsrc));
}

// ---------------- E transpose: g_Et[cb][d][k] = E[cb][k][d] ----------------
__global__ void k_trans(const float* __restrict__ E) {
    __shared__ float tile[64][65];
    int kt = blockIdx.x, dt = blockIdx.y, cb = blockIdx.z;
    int tid = threadIdx.x;
    const float* Ein = E + (size_t)cb * KCB * DD;
    float* Eout = g_Et + (size_t)cb * DD * KCB;
    #pragma unroll
    for (int i = 0; i < 16; i++) {
        int idx = i * 256 + tid;
        int r = idx >> 6, c = idx & 63;
        tile[r][c] = Ein[(size_t)(kt * 64 + r) * DD + dt * 64 + c];
    }
    __syncthreads();
    #pragma unroll
    for (int i = 0; i < 16; i++) {
        int idx = i * 256 + tid;
        int r = idx >> 6, c = idx & 63;
        Eout[(size_t)(dt * 64 + r) * KCB + kt * 64 + c] = tile[c][r];
    }
}

// ---------------- codeword norms (summation order preserved) ----------------
__global__ void k_enorm(const float* __restrict__ E) {
    int w = (blockIdx.x * blockDim.x + threadIdx.x) >> 5;
    int lane = threadIdx.x & 31;
    if (w >= NCB * KCB) return;
    const float* e = E + (size_t)w * DD;
    float s = 0.f;
    #pragma unroll
    for (int k = 0; k < 8; k++) { float v = e[lane + 32 * k]; s += v * v; }
    #pragma unroll
    for (int off = 16; off; off >>= 1) s += __shfl_down_sync(0xffffffffu, s, off);
    if (!lane) g_en[w] = s;
}

// ---------------- init: zero loss accumulators only ----------------
__global__ void k_init() {
    int i = threadIdx.x;
    if (i < NCB) g_vqp[i] = 0.f;
    if (i == NCB) g_semsum = 0.f;
}

// ---------------- fully fused RVQ: warp-private B staging, no block barriers ----------------
// 256 threads = 8 warps, 64 tokens per CTA (grid 256, zero padding work).
// Warp wy owns CODEWORD slice [nt*256+wy*32, +32); lanes: tg=lane>>2 token
// group, cg=lane&3 cw sub-slice. Each warp cp.asyncs its own 2 KB B slice per
// chunk into PRIVATE double-buffered smem; consume sync = wait_group+__syncwarp
// (legal: no cross-warp B reads). Mainloop has ZERO block barriers; only 2
// __syncthreads per codebook (argmin merge + residual republish).
__global__ void __launch_bounds__(256, 2)
k_rvq(const float* __restrict__ z, const float* __restrict__ E, float* __restrict__ out) {
    extern __shared__ float sm[];
    float* Asm  = sm;                       // [257][ASTR] residual (token minor)
    float* Bw   = sm + 257 * ASTR;          // [8 warps][2 stages][16 rows][32 cw]
    float* xxs  = Bw + 8 * 2 * 16 * 32;     // [64]
    float* redv = xxs + 64;                 // [8 warps][64 tokens]
    int*   redi = (int*)(redv + 512);       // [8 warps][64 tokens]

    int tid = threadIdx.x;
    int lane = tid & 31, wy = tid >> 5;
    int tg = lane >> 2, cg = lane & 3;
    int m0 = blockIdx.x * 64;
    float* myB = Bw + wy * 1024;            // this warp's 2-stage buffer

    // load A tile (64 tokens x 256 d) from z, transposed into Asm[d][slot]
    const float4* Ag = reinterpret_cast<const float4*>(z + (size_t)m0 * DD);
    #pragma unroll
    for (int i = 0; i < 16; i++) {
        int f = tid + 256 * i;
        int tok = f >> 6, seg = f & 63;
        float4 v = Ag[f];
        int db = seg * 4;
        Asm[(db + 0) * ASTR + tok] = v.x;
        Asm[(db + 1) * ASTR + tok] = v.y;
        Asm[(db + 2) * ASTR + tok] = v.z;
        Asm[(db + 3) * ASTR + tok] = v.w;
    }

    // initial ||x||^2 per token (ascending j, shfl_down tree)
    #pragma unroll
    for (int r = 0; r < 8; r++) {
        int tok = m0 + wy * 8 + r;
        const float* row = z + (size_t)tok * DD;
        float s = 0.f;
        #pragma unroll
        for (int k = 0; k < 8; k++) { float v = row[lane + 32 * k]; s += v * v; }
        #pragma unroll
        for (int off = 16; off; off >>= 1) s += __shfl_down_sync(0xffffffffu, s, off);
        if (!lane) xxs[wy * 8 + r] = s;
    }
    __syncthreads();

    const int boff = wy * 32 + cg * 8;      // thread's cw offset inside a 256-cw tile

    for (int cb = 0; cb < NCB; cb++) {
        const float* Et  = g_Et + (size_t)cb * DD * KCB;
        const float* Ecb = E + (size_t)cb * KCB * DD;
        const float* enb = g_en + cb * KCB;

        // issue this warp's 16d x 32cw slice of chunk cc (2 KB) via cp.async
        auto issueW = [&](int cc) {
            int nt = cc >> 4, dc = cc & 15, st = cc & 1;
            const float* src = Et + (size_t)(dc * 16) * KCB + nt * 256 + wy * 32;
            float* dst = myB + st * 512;
            #pragma unroll
            for (int i = 0; i < 4; i++) {
                int u = lane + 32 * i;          // 128 16B units / 32 lanes
                int row = u >> 3, seg = u & 7;
                cp16(dst + row * 32 + seg * 4, src + (size_t)row * KCB + seg * 4);
            }
            asm volatile("cp.async.commit_group;");
        };

        issueW(0);                          // chunk 0 in flight

        float mv[8]; int mi[8];
        #pragma unroll
        for (int r = 0; r < 8; r++) { mv[r] = INFINITY; mi[r] = 0; }
        unsigned long long acc[8][4];
        #pragma unroll
        for (int r = 0; r < 8; r++)
            #pragma unroll
            for (int q = 0; q < 4; q++) acc[r][q] = 0ull;

        for (int cc = 0; cc < 128; cc++) {             // 8 n-tiles * 16 d-chunks
            asm volatile("cp.async.wait_group 0;");    // my slice of chunk cc landed
            __syncwarp();                              // publish within warp (B is warp-private)
            if (cc + 1 < 128) issueW(cc + 1);

            const float* Bp = myB + (cc & 1) * 512;
            int dbase = (cc & 15) * 16;

            // preload kk=0 operands
            ulonglong2 bb0 = *reinterpret_cast<const ulonglong2*>(Bp + cg * 8);
            ulonglong2 bb1 = *reinterpret_cast<const ulonglong2*>(Bp + cg * 8 + 4);
            float4 a0 = *reinterpret_cast<const float4*>(&Asm[dbase * ASTR + tg * 8]);
            float4 a1 = *reinterpret_cast<const float4*>(&Asm[dbase * ASTR + tg * 8 + 4]);

            #pragma unroll
            for (int kk = 0; kk < 16; kk++) {
                ulonglong2 nb0, nb1; float4 na0, na1;
                if (kk < 15) {                          // prefetch kk+1 operands
                    nb0 = *reinterpret_cast<const ulonglong2*>(Bp + (kk + 1) * 32 + cg * 8);
                    nb1 = *reinterpret_cast<const ulonglong2*>(Bp + (kk + 1) * 32 + cg * 8 + 4);
                    na0 = *reinterpret_cast<const float4*>(&Asm[(dbase + kk + 1) * ASTR + tg * 8]);
                    na1 = *reinterpret_cast<const float4*>(&Asm[(dbase + kk + 1) * ASTR + tg * 8 + 4]);
                }
                float a[8] = {a0.x, a0.y, a0.z, a0.w, a1.x, a1.y, a1.z, a1.w};
                #pragma unroll
                for (int r = 0; r < 8; r++) {
                    unsigned long long a2 = dup2(a[r]);
                    fma2(acc[r][0], a2, bb0.x);
                    fma2(acc[r][1], a2, bb0.y);
                    fma2(acc[r][2], a2, bb1.x);
                    fma2(acc[r][3], a2, bb1.y);
                }
                if (kk < 15) { bb0 = nb0; bb1 = nb1; a0 = na0; a1 = na1; }
            }

            if ((cc & 15) == 15) {                     // n-tile argmin epilogue
                int n0 = (cc >> 4) * 256;
                float2 e01[4];
                #pragma unroll
                for (int q = 0; q < 4; q++)
                    e01[q] = __ldg(reinterpret_cast<const float2*>(&enb[n0 + boff + q * 2]));
                #pragma unroll
                for (int r = 0; r < 8; r++) {
                    float xr = xxs[tg * 8 + r];
                    #pragma unroll
                    for (int q = 0; q < 4; q++) {
                        int kb = n0 + boff + q * 2;
                        float lo, hi;
                        unpk(lo, hi, acc[r][q]);
                        float s0 = (xr - 2.0f * lo) + e01[q].x;
                        float s1 = (xr - 2.0f * hi) + e01[q].y;
                        if (s0 < mv[r]) { mv[r] = s0; mi[r] = kb; }
                        if (s1 < mv[r]) { mv[r] = s1; mi[r] = kb + 1; }
                        acc[r][q] = 0ull;
                    }
                }
            }
        }

        // reduce across the 4 cg lanes sharing a token group (tie: smaller index)
        #pragma unroll
        for (int off = 1; off < 4; off <<= 1) {
            #pragma unroll
            for (int r = 0; r < 8; r++) {
                float ov = __shfl_xor_sync(0xffffffffu, mv[r], off);
                int   oi = __shfl_xor_sync(0xffffffffu, mi[r], off);
                if (ov < mv[r] || (ov == mv[r] && oi < mi[r])) { mv[r] = ov; mi[r] = oi; }
            }
        }
        // publish per-warp candidates (warp cw sets are disjoint)
        if (cg == 0) {
            #pragma unroll
            for (int r = 0; r < 8; r++) {
                redv[wy * 64 + tg * 8 + r] = mv[r];
                redi[wy * 64 + tg * 8 + r] = mi[r];
            }
        }
        __syncthreads();

        // final merge + straight-through update: warp wy owns tokens wy*8..+8
        {
            int fidx[8];
            #pragma unroll
            for (int r = 0; r < 8; r++) {
                int slot = wy * 8 + r;
                float bv = redv[slot]; int bi = redi[slot];
                #pragma unroll
                for (int w = 1; w < 8; w++) {
                    float v = redv[w * 64 + slot]; int i = redi[w * 64 + slot];
                    if (v < bv || (v == bv && i < bi)) { bv = v; bi = i; }
                }
                fidx[r] = bi;
            }
            float sl = 0.f;
            #pragma unroll
            for (int r = 0; r < 8; r++) {
                int slot = wy * 8 + r;
                int tok = m0 + slot;
                int idx = fidx[r];
                const float* qrow = Ecb + (size_t)idx * DD;
                float* orow = out + (size_t)tok * DD;
                float* zrow = g_zq1 + (size_t)tok * DD;
                float sx = 0.f;
                #pragma unroll
                for (int j = 0; j < 8; j++) {
                    int d = lane + 32 * j;
                    float rr = Asm[d * ASTR + slot];
                    float q  = __ldg(&qrow[d]);
                    float df = q - rr;                 // fl(q - r)
                    float zq = rr + df;                // straight-through, jax order
                    float nr = rr - zq;                // new residual
                    if (cb == 0) { orow[d] = zq; zrow[d] = zq; }  // fl(0+zq)==zq
                    else orow[d] += zq;                // z_q_total accumulation
                    Asm[d * ASTR + slot] = nr;
                    sl += df * df;
                    sx += nr * nr;
                }
                #pragma unroll
                for (int off = 16; off; off >>= 1) sx += __shfl_down_sync(0xffffffffu, sx, off);
                if (lane == 0) {
                    xxs[slot] = sx;
                    out[CODES_OFF + tok * NCB + cb] = (float)idx;
                }
            }
            #pragma unroll
            for (int off = 16; off; off >>= 1) sl += __shfl_xor_sync(0xffffffffu, sl, off);
            if (lane == 0) atomicAdd(&g_vqp[cb], sl);
        }

        __syncthreads();   // Asm/xxs republished block-wide before next codebook
    }
}

// ---------------- semantic head GEMM1: H = gelu(zq1 @ W1 + b1) ----------------
__global__ void __launch_bounds__(256, 2)
k_gemm1(const float* __restrict__ W1, const float* __restrict__ b1) {
    extern __shared__ float sm[];
    float* Asm = sm;                  // [256][APAD]
    float* Bs  = sm + 256 * APAD;     // [16][APAD]
    int tid = threadIdx.x, tx = tid & 15, ty = tid >> 4;
    int m0 = blockIdx.x * 64, n0 = blockIdx.y * 64;

    const float4* Ag = reinterpret_cast<const float4*>(g_zq1 + (size_t)m0 * DD);
    #pragma unroll
    for (int i = 0; i < 16; i++) {
        int f = tid + 256 * i;
        int tok = f >> 6, seg = f & 63;
        float4 v = Ag[tok * 64 + seg];
        int db = seg * 4;
        Asm[(db + 0) * APAD + tok] = v.x;
        Asm[(db + 1) * APAD + tok] = v.y;
        Asm[(db + 2) * APAD + tok] = v.z;
        Asm[(db + 3) * APAD + tok] = v.w;
    }
    __syncthreads();

    unsigned long long acc[4][2];
    #pragma unroll
    for (int r = 0; r < 4; r++) { acc[r][0] = 0ull; acc[r][1] = 0ull; }

    for (int dc = 0; dc < 16; dc++) {
        int dk = tid >> 4, nseg = tid & 15;
        float4 v = *reinterpret_cast<const float4*>(&W1[(size_t)(dc * 16 + dk) * SEMD + n0 + nseg * 4]);
        *reinterpret_cast<float4*>(&Bs[dk * APAD + nseg * 4]) = v;
        __syncthreads();
        #pragma unroll
        for (int kk = 0; kk < 16; kk++) {
            float4 av = *reinterpret_cast<const float4*>(&Asm[(dc * 16 + kk) * APAD + ty * 4]);
            ulonglong2 bb = *reinterpret_cast<const ulonglong2*>(&Bs[kk * APAD + tx * 4]);
            float a[4] = {av.x, av.y, av.z, av.w};
            #pragma unroll
            for (int r = 0; r < 4; r++) {
                unsigned long long a2 = dup2(a[r]);
                fma2(acc[r][0], a2, bb.x);
                fma2(acc[r][1], a2, bb.y);
            }
        }
        __syncthreads();
    }
    #pragma unroll
    for (int r = 0; r < 4; r++)
        #pragma unroll
        for (int q = 0; q < 2; q++) {
            int m = m0 + ty * 4 + r, n = n0 + tx * 4 + q * 2;
            float lo, hi;
            unpk(lo, hi, acc[r][q]);
            float x0 = lo + __ldg(&b1[n]);
            float x1 = hi + __ldg(&b1[n + 1]);
            g_H[(size_t)m * SEMD + n]     = 0.5f * x0 * (1.0f + erff(x0 * 0.70710678118654752f));
            g_H[(size_t)m * SEMD + n + 1] = 0.5f * x1 * (1.0f + erff(x1 * 0.70710678118654752f));
        }
}

// ---------------- semantic head GEMM2 + fused MSE reduction ----------------
__global__ void __launch_bounds__(256, 2)
k_gemm2(const float* __restrict__ W2, const float* __restrict__ b2, const float* __restrict__ tgt) {
    extern __shared__ float sm[];
    float* Asm = sm;
    float* Bs  = sm + 256 * APAD;
    int tid = threadIdx.x, tx = tid & 15, ty = tid >> 4;
    int m0 = blockIdx.x * 64, n0 = blockIdx.y * 64;

    const float4* Ag = reinterpret_cast<const float4*>(g_H + (size_t)m0 * SEMD);
    #pragma unroll
    for (int i = 0; i < 16; i++) {
        int f = tid + 256 * i;
        int tok = f >> 6, seg = f & 63;
        float4 v = Ag[tok * 64 + seg];
        int db = seg * 4;
        Asm[(db + 0) * APAD + tok] = v.x;
        Asm[(db + 1) * APAD + tok] = v.y;
        Asm[(db + 2) * APAD + tok] = v.z;
        Asm[(db + 3) * APAD + tok] = v.w;
    }
    __syncthreads();

    unsigned long long acc[4][2];
    #pragma unroll
    for (int r = 0; r < 4; r++) { acc[r][0] = 0ull; acc[r][1] = 0ull; }

    for (int dc = 0; dc < 16; dc++) {
        int dk = tid >> 4, nseg = tid & 15;
        float4 v = *reinterpret_cast<const float4*>(&W2[(size_t)(dc * 16 + dk) * W2VD + n0 + nseg * 4]);
        *reinterpret_cast<float4*>(&Bs[dk * APAD + nseg * 4]) = v;
        __syncthreads();
        #pragma unroll
        for (int kk = 0; kk < 16; kk++) {
            float4 av = *reinterpret_cast<const float4*>(&Asm[(dc * 16 + kk) * APAD + ty * 4]);
            ulonglong2 bb = *reinterpret_cast<const ulonglong2*>(&Bs[kk * APAD + tx * 4]);
            float a[4] = {av.x, av.y, av.z, av.w};
            #pragma unroll
            for (int r = 0; r < 4; r++) {
                unsigned long long a2 = dup2(a[r]);
                fma2(acc[r][0], a2, bb.x);
                fma2(acc[r][1], a2, bb.y);
            }
        }
        __syncthreads();
    }

    float ls = 0.f;
    #pragma unroll
    for (int r = 0; r < 4; r++)
        #pragma unroll
        for (int q = 0; q < 2; q++) {
            int m = m0 + ty * 4 + r, n = n0 + tx * 4 + q * 2;
            float lo, hi;
            unpk(lo, hi, acc[r][q]);
            float p0 = lo + __ldg(&b2[n]);
            float p1 = hi + __ldg(&b2[n + 1]);
            float d0 = p0 - __ldg(&tgt[(size_t)m * W2VD + n]);
            float d1 = p1 - __ldg(&tgt[(size_t)m * W2VD + n + 1]);
            ls += d0 * d0;
            ls += d1 * d1;
        }
    __shared__ float red[8];
    int lane = tid & 31, w = tid >> 5;
    #pragma unroll
    for (int off = 16; off; off >>= 1) ls += __shfl_xor_sync(0xffffffffu, ls, off);
    if (!lane) red[w] = ls;
    __syncthreads();
    if (tid < 8) {
        float t = red[tid];
        #pragma unroll
        for (int off = 4; off; off >>= 1) t += __shfl_xor_sync(0xffu, t, off);
        if (tid == 0) atomicAdd(&g_semsum, t);
    }
}

// ---------------- finalize scalars ----------------
__global__ void k_fin(float* __restrict__ out) {
    if (threadIdx.x == 0) {
        float vq = 0.f;
        #pragma unroll
        for (int i = 0; i < NCB; i++) {
            float m = g_vqp[i] * (1.0f / 4194304.0f);   // mean over B*T*D
            vq += m + 0.25f * m;                         // embedding + COMMIT*commitment
        }
        out[VQ_OFF] = vq;
        out[SEM_OFF] = g_semsum * (1.0f / 16777216.0f);  // mean over B*T*W2V
    }
}

// ---------------- launch ----------------
extern "C" void kernel_launch(void* const* d_in, const int* in_sizes, int n_in,
                              void* d_out, int out_size) {
    const float* z   = (const float*)d_in[0];
    const float* w2v = (const float*)d_in[1];
    const float* E   = (const float*)d_in[2];
    const float* W1  = (const float*)d_in[3];
    const float* b1  = (const float*)d_in[4];
    const float* W2  = (const float*)d_in[5];
    const float* b2  = (const float*)d_in[6];
    float* out = (float*)d_out;

    // Asm 257*68 + Bw 8192 + xxs 64 + redv 512 + redi 512 = 26756 floats = 107,024 B
    const int ARG_SMEM  = (257 * ASTR + 8 * 2 * 16 * 32 + 64 + 512 + 512) * 4;
    const int GEMM_SMEM = (256 * APAD + 16 * APAD) * 4;              // 73,984 B
    cudaFuncSetAttribute(k_rvq,   cudaFuncAttributeMaxDynamicSharedMemorySize, ARG_SMEM);
    cudaFuncSetAttribute(k_gemm1, cudaFuncAttributeMaxDynamicSharedMemorySize, GEMM_SMEM);
    cudaFuncSetAttribute(k_gemm2, cudaFuncAttributeMaxDynamicSharedMemorySize, GEMM_SMEM);

    k_trans<<<dim3(KCB / 64, DD / 64, NCB), 256>>>(E);
    k_enorm<<<(NCB * KCB * 32 + 255) / 256, 256>>>(E);
    k_init<<<1, 32>>>();

    k_rvq<<<BT / 64, 256, ARG_SMEM>>>(z, E, out);

    k_gemm1<<<dim3(BT / 64, SEMD / 64), 256, GEMM_SMEM>>>(W1, b1);
    k_gemm2<<<dim3(BT / 64, W2VD / 64), 256, GEMM_SMEM>>>(W2, b2, w2v);
    k_fin<<<1, 32>>>(out);
}

// round 12
// speedup vs baseline: 1.0920x; 1.0479x over previous
#include <cuda_runtime.h>
#include <math.h>

#define NCB   10
#define KCB   2048
#define DD    256
#define SEMD  256
#define W2VD  1024
#define BT    16384              // B*T tokens
#define ZQ_ELEMS (BT*DD)         // 4194304
#define CODES_OFF ZQ_ELEMS
#define VQ_OFF   (CODES_OFF + BT*NCB)
#define SEM_OFF  (VQ_OFF + 1)
#define APAD  68                 // A smem row stride (floats, 16B aligned)
#define BPAD  264                // B smem row stride (floats, 16B aligned)

// balanced tiling: 272 tiles x 56 tokens + 24 tiles x 48 tokens = 16384,
// grid = 296 = 2 x 148 SMs -> one wave at occupancy 2
#define N56   272
#define OFF48 (N56*56)           // 15232

// -------- device scratch (no runtime allocation allowed) --------
__device__ float g_zq1[ZQ_ELEMS];     // z_q of codebook 0 (semantic head input)
__device__ float g_Et[NCB*DD*KCB];    // E transposed per codebook: [cb][d][k]
__device__ float g_en[NCB*KCB];       // ||e_k||^2 per codebook
__device__ float g_vqp[NCB];          // per-codebook sum of (q-r)^2
__device__ float g_semsum;            // sum of (pred-target)^2

// packed fp32x2 FMA (sm_103a): two bitwise-exact IEEE fp32 FMAs per issue slot
__device__ __forceinline__ void fma2(unsigned long long& d,
                                     unsigned long long a, unsigned long long b) {
    asm("fma.rn.f32x2 %0, %1, %2, %0;" : "+l"(d) : "l"(a), "l"(b));
}
__device__ __forceinline__ unsigned long long dup2(float a) {
    unsigned long long r;
    asm("mov.b64 %0, {%1, %1};" : "=l"(r) : "f"(a));
    return r;
}
__device__ __forceinline__ void unpk(float& lo, float& hi, unsigned long long v) {
    asm("mov.b64 {%0, %1}, %2;" : "=f"(lo), "=f"(hi) : "l"(v));
}
__device__ __forceinline__ void cp16(void* smem_dst, const void* gsrc) {
    unsigned s = (unsigned)__cvta_generic_to_shared(smem_dst);
    asm volatile("cp.async.cg.shared.global [%0], [%1], 16;" :: "r"(s), "l"(gsrc));
}

// ---------------- E transpose: g_Et[cb][d][k] = E[cb][k][d] ----------------
__global__ void k_trans(const float* __restrict__ E) {
    __shared__ float tile[64][65];
    int kt = blockIdx.x, dt = blockIdx.y, cb = blockIdx.z;
    int tid = threadIdx.x;
    const float* Ein = E + (size_t)cb * KCB * DD;
    float* Eout = g_Et + (size_t)cb * DD * KCB;
    #pragma unroll
    for (int i = 0; i < 16; i++) {
        int idx = i * 256 + tid;
        int r = idx >> 6, c = idx & 63;
        tile[r][c] = Ein[(size_t)(kt * 64 + r) * DD + dt * 64 + c];
    }
    __syncthreads();
    #pragma unroll
    for (int i = 0; i < 16; i++) {
        int idx = i * 256 + tid;
        int r = idx >> 6, c = idx & 63;
        Eout[(size_t)(dt * 64 + r) * KCB + kt * 64 + c] = tile[c][r];
    }
}

// ---------------- codeword norms (summation order preserved) ----------------
__global__ void k_enorm(const float* __restrict__ E) {
    int w = (blockIdx.x * blockDim.x + threadIdx.x) >> 5;
    int lane = threadIdx.x & 31;
    if (w >= NCB * KCB) return;
    const float* e = E + (size_t)w * DD;
    float s = 0.f;
    #pragma unroll
    for (int k = 0; k < 8; k++) { float v = e[lane + 32 * k]; s += v * v; }
    #pragma unroll
    for (int off = 16; off; off >>= 1) s += __shfl_down_sync(0xffffffffu, s, off);
    if (!lane) g_en[w] = s;
}

// ---------------- init: zero loss accumulators only ----------------
__global__ void k_init() {
    int i = threadIdx.x;
    if (i < NCB) g_vqp[i] = 0.f;
    if (i == NCB) g_semsum = 0.f;
}

// ---------------- fully fused RVQ body (R7 best variant) ----------------
// block = 256 threads = 8 warps; warp wy owns NR tokens (smem slots wy*8+r,
// 8-padded so LDS patterns are NR-independent). Residual lives in smem.
template<int NR>
__device__ __forceinline__ void rvq_body(
    int m0, const float* __restrict__ z, const float* __restrict__ E,
    float* __restrict__ out, float* sm, int tid, int lane, int wy)
{
    float* Asm = sm;                        // [256 d][APAD] residual (8-padded slots)
    float* Bs  = sm + 256 * APAD;           // 2 x [16 d][BPAD]
    float* xxs = Bs + 2 * 16 * BPAD;        // [64]
    float* ens = xxs + 64;                  // [2048]

    const int mt = NR * 8;                  // tokens in this tile

    // load A tile from z, transposed into Asm[d][slot]
    const float4* Ag = reinterpret_cast<const float4*>(z + (size_t)m0 * DD);
    for (int f = tid; f < mt * 64; f += 256) {
        int tok = f >> 6, seg = f & 63;
        int slot = (tok / NR) * 8 + (tok % NR);
        float4 v = Ag[f];
        int db = seg * 4;
        Asm[(db + 0) * APAD + slot] = v.x;
        Asm[(db + 1) * APAD + slot] = v.y;
        Asm[(db + 2) * APAD + slot] = v.z;
        Asm[(db + 3) * APAD + slot] = v.w;
    }

    // initial ||x||^2 per token (ascending j, shfl_down tree)
    #pragma unroll
    for (int r = 0; r < NR; r++) {
        int tok = m0 + wy * NR + r;
        const float* row = z + (size_t)tok * DD;
        float s = 0.f;
        #pragma unroll
        for (int k = 0; k < 8; k++) { float v = row[lane + 32 * k]; s += v * v; }
        #pragma unroll
        for (int off = 16; off; off >>= 1) s += __shfl_down_sync(0xffffffffu, s, off);
        if (!lane) xxs[wy * 8 + r] = s;
    }

    for (int cb = 0; cb < NCB; cb++) {
        const float* Et  = g_Et + (size_t)cb * DD * KCB;
        const float* Ecb = E + (size_t)cb * KCB * DD;

        auto issueB = [&](int cc, float* buf) {
            int nt = cc >> 4, dc = cc & 15;
            #pragma unroll
            for (int i = 0; i < 4; i++) {
                int fid = i * 256 + tid;
                int row = fid >> 6, col = (fid & 63) * 4;
                cp16(&buf[row * BPAD + col],
                     Et + (size_t)(dc * 16 + row) * KCB + nt * 256 + col);
            }
            asm volatile("cp.async.commit_group;");
        };

        issueB(0, Bs);                      // chunk 0 in flight

        // stage codeword norms into smem
        {
            const float4* en4 = reinterpret_cast<const float4*>(g_en + cb * KCB);
            float4 v0 = en4[tid * 2 + 0], v1 = en4[tid * 2 + 1];
            *reinterpret_cast<float4*>(&ens[tid * 8 + 0]) = v0;
            *reinterpret_cast<float4*>(&ens[tid * 8 + 4]) = v1;
        }

        float mv[NR]; int mi[NR];
        #pragma unroll
        for (int r = 0; r < NR; r++) { mv[r] = INFINITY; mi[r] = 0; }
        unsigned long long acc[NR][4];
        #pragma unroll
        for (int r = 0; r < NR; r++)
            #pragma unroll
            for (int q = 0; q < 4; q++) acc[r][q] = 0ull;

        for (int cc = 0; cc < 128; cc++) {             // 8 n-tiles * 16 d-chunks
            asm volatile("cp.async.wait_group 0;");
            __syncthreads();
            if (cc + 1 < 128) issueB(cc + 1, Bs + ((cc + 1) & 1) * 16 * BPAD);

            const float* Bp = Bs + (cc & 1) * 16 * BPAD;
            int dbase = (cc & 15) * 16;

            ulonglong2 bb0 = *reinterpret_cast<const ulonglong2*>(
                reinterpret_cast<const unsigned long long*>(&Bp[0]) + lane * 2);
            ulonglong2 bb1 = *reinterpret_cast<const ulonglong2*>(
                reinterpret_cast<const unsigned long long*>(&Bp[0]) + 64 + lane * 2);

            #pragma unroll
            for (int kk = 0; kk < 16; kk++) {
                ulonglong2 nb0, nb1;
                if (kk < 15) {
                    const unsigned long long* brn =
                        reinterpret_cast<const unsigned long long*>(&Bp[(kk + 1) * BPAD]);
                    nb0 = *reinterpret_cast<const ulonglong2*>(brn + lane * 2);
                    nb1 = *reinterpret_cast<const ulonglong2*>(brn + 64 + lane * 2);
                }
                float4 av0 = *reinterpret_cast<const float4*>(&Asm[(dbase + kk) * APAD + wy * 8]);
                float4 av1 = *reinterpret_cast<const float4*>(&Asm[(dbase + kk) * APAD + wy * 8 + 4]);
                float a[8] = {av0.x, av0.y, av0.z, av0.w, av1.x, av1.y, av1.z, av1.w};
                #pragma unroll
                for (int r = 0; r < NR; r++) {
                    unsigned long long a2 = dup2(a[r]);
                    fma2(acc[r][0], a2, bb0.x);
                    fma2(acc[r][1], a2, bb0.y);
                    fma2(acc[r][2], a2, bb1.x);
                    fma2(acc[r][3], a2, bb1.y);
                }
                if (kk < 15) { bb0 = nb0; bb1 = nb1; }
            }

            if ((cc & 15) == 15) {                     // n-tile argmin epilogue
                int n0 = (cc >> 4) * 256;
                float2 e01[4];
                #pragma unroll
                for (int q = 0; q < 4; q++) {
                    int kb = n0 + (q >> 1) * 128 + lane * 4 + (q & 1) * 2;
                    e01[q] = *reinterpret_cast<const float2*>(&ens[kb]);
                }
                #pragma unroll
                for (int r = 0; r < NR; r++) {
                    float xr = xxs[wy * 8 + r];
                    #pragma unroll
                    for (int q = 0; q < 4; q++) {
                        int kb = n0 + (q >> 1) * 128 + lane * 4 + (q & 1) * 2;
                        float lo, hi;
                        unpk(lo, hi, acc[r][q]);
                        float s0 = (xr - 2.0f * lo) + e01[q].x;
                        float s1 = (xr - 2.0f * hi) + e01[q].y;
                        if (s0 < mv[r]) { mv[r] = s0; mi[r] = kb; }
                        if (s1 < mv[r]) { mv[r] = s1; mi[r] = kb + 1; }
                        acc[r][q] = 0ull;
                    }
                }
            }
        }

        // argmin reduce across 32 lanes (first-index tie break)
        #pragma unroll
        for (int off = 1; off < 32; off <<= 1) {
            #pragma unroll
            for (int r = 0; r < NR; r++) {
                float ov = __shfl_xor_sync(0xffffffffu, mv[r], off);
                int   oi = __shfl_xor_sync(0xffffffffu, mi[r], off);
                if (ov < mv[r] || (ov == mv[r] && oi < mi[r])) { mv[r] = ov; mi[r] = oi; }
            }
        }

        // fused straight-through update, residual updated IN SMEM
        float sl = 0.f;
        #pragma unroll
        for (int r = 0; r < NR; r++) {
            int slot = wy * 8 + r;
            int tok = m0 + wy * NR + r;
            int idx = mi[r];
            const float* qrow = Ecb + (size_t)idx * DD;
            float* orow = out + (size_t)tok * DD;
            float* zrow = g_zq1 + (size_t)tok * DD;
            float sx = 0.f;
            #pragma unroll
            for (int j = 0; j < 8; j++) {
                int d = lane + 32 * j;
                float rr = Asm[d * APAD + slot];
                float q  = __ldg(&qrow[d]);
                float df = q - rr;                 // fl(q - r)
                float zq = rr + df;                // straight-through, jax order
                float nr = rr - zq;                // new residual
                if (cb == 0) { orow[d] = zq; zrow[d] = zq; }  // fl(0+zq)==zq
                else orow[d] += zq;                // z_q_total accumulation
                Asm[d * APAD + slot] = nr;
                sl += df * df;
                sx += nr * nr;
            }
            #pragma unroll
            for (int off = 16; off; off >>= 1) sx += __shfl_down_sync(0xffffffffu, sx, off);
            if (lane == 0) {
                xxs[slot] = sx;
                out[CODES_OFF + tok * NCB + cb] = (float)idx;
            }
        }
        #pragma unroll
        for (int off = 16; off; off >>= 1) sl += __shfl_xor_sync(0xffffffffu, sl, off);
        if (lane == 0) atomicAdd(&g_vqp[cb], sl);

        __syncthreads();   // ens/Bs WAR before next codebook restages them
    }
}

__global__ void __launch_bounds__(256, 2)
k_rvq(const float* __restrict__ z, const float* __restrict__ E, float* __restrict__ out) {
    extern __shared__ float sm[];
    int tid = threadIdx.x;
    int lane = tid & 31, wy = tid >> 5;
    int b = blockIdx.x;
    if (b < N56) rvq_body<7>(b * 56, z, E, out, sm, tid, lane, wy);
    else         rvq_body<6>(OFF48 + (b - N56) * 48, z, E, out, sm, tid, lane, wy);
}

// ---------------- fused semantic head: H = gelu(zq1@W1+b1); MSE(H@W2+b2, tgt) ----------------
// One CTA per 64-token tile. Pass 1 accumulates the full 64x256 H tile into
// registers (64/thread), restages it into the SAME smem tile (overwriting zq),
// pass 2 runs the 64x1024 W2 GEMM + loss from smem. Per-output FMA chains are
// d-ascending exactly as the old separate kernels.
__global__ void __launch_bounds__(256, 2)
k_sem(const float* __restrict__ W1, const float* __restrict__ b1,
      const float* __restrict__ W2, const float* __restrict__ b2,
      const float* __restrict__ tgt) {
    extern __shared__ float sm[];
    float* Asm = sm;                  // [256][APAD]: zq1 tile, then H tile
    float* Bs  = sm + 256 * APAD;     // [16][APAD]
    int tid = threadIdx.x, tx = tid & 15, ty = tid >> 4;
    int m0 = blockIdx.x * 64;

    // load zq1 tile transposed: Asm[d][tok]
    const float4* Ag = reinterpret_cast<const float4*>(g_zq1 + (size_t)m0 * DD);
    #pragma unroll
    for (int i = 0; i < 16; i++) {
        int f = tid + 256 * i;
        int tok = f >> 6, seg = f & 63;
        float4 v = Ag[f];
        int db = seg * 4;
        Asm[(db + 0) * APAD + tok] = v.x;
        Asm[(db + 1) * APAD + tok] = v.y;
        Asm[(db + 2) * APAD + tok] = v.z;
        Asm[(db + 3) * APAD + tok] = v.w;
    }
    __syncthreads();

    // ---- pass 1: H tile in registers (4 m x 16 n per thread) ----
    unsigned long long hacc[4][8];
    #pragma unroll
    for (int r = 0; r < 4; r++)
        #pragma unroll
        for (int u = 0; u < 8; u++) hacc[r][u] = 0ull;

    for (int nb = 0; nb < 4; nb++) {
        int n0 = nb * 64;
        for (int dc = 0; dc < 16; dc++) {
            int dk = tid >> 4, nseg = tid & 15;
            float4 v = *reinterpret_cast<const float4*>(&W1[(size_t)(dc * 16 + dk) * SEMD + n0 + nseg * 4]);
            *reinterpret_cast<float4*>(&Bs[dk * APAD + nseg * 4]) = v;
            __syncthreads();
            #pragma unroll
            for (int kk = 0; kk < 16; kk++) {
                float4 av = *reinterpret_cast<const float4*>(&Asm[(dc * 16 + kk) * APAD + ty * 4]);
                ulonglong2 bb = *reinterpret_cast<const ulonglong2*>(&Bs[kk * APAD + tx * 4]);
                float a[4] = {av.x, av.y, av.z, av.w};
                #pragma unroll
                for (int r = 0; r < 4; r++) {
                    unsigned long long a2 = dup2(a[r]);
                    fma2(hacc[r][nb * 2 + 0], a2, bb.x);
                    fma2(hacc[r][nb * 2 + 1], a2, bb.y);
                }
            }
            __syncthreads();
        }
    }

    // bias + exact-erf gelu, write H transposed into Asm[n][m] (zq no longer needed)
    #pragma unroll
    for (int r = 0; r < 4; r++)
        #pragma unroll
        for (int u = 0; u < 8; u++) {
            int m = ty * 4 + r;
            int n = (u >> 1) * 64 + tx * 4 + (u & 1) * 2;
            float lo, hi;
            unpk(lo, hi, hacc[r][u]);
            float x0 = lo + __ldg(&b1[n]);
            float x1 = hi + __ldg(&b1[n + 1]);
            Asm[n * APAD + m]       = 0.5f * x0 * (1.0f + erff(x0 * 0.70710678118654752f));
            Asm[(n + 1) * APAD + m] = 0.5f * x1 * (1.0f + erff(x1 * 0.70710678118654752f));
        }
    __syncthreads();

    // ---- pass 2: out = H @ W2 + b2, fused MSE ----
    float ls = 0.f;
    for (int n0b = 0; n0b < 16; n0b++) {
        int n0 = n0b * 64;
        unsigned long long acc[4][2];
        #pragma unroll
        for (int r = 0; r < 4; r++) { acc[r][0] = 0ull; acc[r][1] = 0ull; }

        for (int dc = 0; dc < 16; dc++) {
            int dk = tid >> 4, nseg = tid & 15;
            float4 v = *reinterpret_cast<const float4*>(&W2[(size_t)(dc * 16 + dk) * W2VD + n0 + nseg * 4]);
            *reinterpret_cast<float4*>(&Bs[dk * APAD + nseg * 4]) = v;
            __syncthreads();
            #pragma unroll
            for (int kk = 0; kk < 16; kk++) {
                float4 av = *reinterpret_cast<const float4*>(&Asm[(dc * 16 + kk) * APAD + ty * 4]);
                ulonglong2 bb = *reinterpret_cast<const ulonglong2*>(&Bs[kk * APAD + tx * 4]);
                float a[4] = {av.x, av.y, av.z, av.w};
                #pragma unroll
                for (int r = 0; r < 4; r++) {
                    unsigned long long a2 = dup2(a[r]);
                    fma2(acc[r][0], a2, bb.x);
                    fma2(acc[r][1], a2, bb.y);
                }
            }
            __syncthreads();
        }

        #pragma unroll
        for (int r = 0; r < 4; r++)
            #pragma unroll
            for (int q = 0; q < 2; q++) {
                int m = m0 + ty * 4 + r, n = n0 + tx * 4 + q * 2;
                float lo, hi;
                unpk(lo, hi, acc[r][q]);
                float p0 = lo + __ldg(&b2[n]);
                float p1 = hi + __ldg(&b2[n + 1]);
                float d0 = p0 - __ldg(&tgt[(size_t)m * W2VD + n]);
                float d1 = p1 - __ldg(&tgt[(size_t)m * W2VD + n + 1]);
                ls += d0 * d0;
                ls += d1 * d1;
            }
    }

    __shared__ float red[8];
    int lane = tid & 31, w = tid >> 5;
    #pragma unroll
    for (int off = 16; off; off >>= 1) ls += __shfl_xor_sync(0xffffffffu, ls, off);
    if (!lane) red[w] = ls;
    __syncthreads();
    if (tid < 8) {
        float t = red[tid];
        #pragma unroll
        for (int off = 4; off; off >>= 1) t += __shfl_xor_sync(0xffu, t, off);
        if (tid == 0) atomicAdd(&g_semsum, t);
    }
}

// ---------------- finalize scalars ----------------
__global__ void k_fin(float* __restrict__ out) {
    if (threadIdx.x == 0) {
        float vq = 0.f;
        #pragma unroll
        for (int i = 0; i < NCB; i++) {
            float m = g_vqp[i] * (1.0f / 4194304.0f);   // mean over B*T*D
            vq += m + 0.25f * m;                         // embedding + COMMIT*commitment
        }
        out[VQ_OFF] = vq;
        out[SEM_OFF] = g_semsum * (1.0f / 16777216.0f);  // mean over B*T*W2V
    }
}

// ---------------- launch ----------------
extern "C" void kernel_launch(void* const* d_in, const int* in_sizes, int n_in,
                              void* d_out, int out_size) {
    const float* z   = (const float*)d_in[0];
    const float* w2v = (const float*)d_in[1];
    const float* E   = (const float*)d_in[2];
    const float* W1  = (const float*)d_in[3];
    const float* b1  = (const float*)d_in[4];
    const float* W2  = (const float*)d_in[5];
    const float* b2  = (const float*)d_in[6];
    float* out = (float*)d_out;

    const int ARG_SMEM = (256 * APAD + 2 * 16 * BPAD + 64 + KCB) * 4;  // 111,872 B
    const int SEM_SMEM = (256 * APAD + 16 * APAD) * 4;                 // 73,984 B
    cudaFuncSetAttribute(k_rvq, cudaFuncAttributeMaxDynamicSharedMemorySize, ARG_SMEM);
    cudaFuncSetAttribute(k_sem, cudaFuncAttributeMaxDynamicSharedMemorySize, SEM_SMEM);

    k_trans<<<dim3(KCB / 64, DD / 64, NCB), 256>>>(E);
    k_enorm<<<(NCB * KCB * 32 + 255) / 256, 256>>>(E);
    k_init<<<1, 32>>>();

    k_rvq<<<296, 256, ARG_SMEM>>>(z, E, out);

    k_sem<<<BT / 64, 256, SEM_SMEM>>>(W1, b1, W2, b2, w2v);
    k_fin<<<1, 32>>>(out);
}